// round 1
// baseline (speedup 1.0000x reference)
#include <cuda_runtime.h>

// ---------------------------------------------------------------------------
// MultiScaleRoIAlign (torchvision semantics, aligned=False, sampling_ratio=2)
// feats: [2,256,200,200],[2,256,100,100],[2,256,50,50],[2,256,25,25] fp32 NCHW
// boxes: [2,256,4] (x1,y1,x2,y2); out: [512,256,7,7] fp32
//
// Strategy: transpose all levels to NHWC scratch (coalesced gathers), then one
// gather kernel: block = (roi, slice), item = (bin, 4-channel group) -> each
// bilinear tap is a coalesced float4 load across 64 consecutive lanes-worth.
// ---------------------------------------------------------------------------

#define NCH 256

// NHWC scratch: 2*256*(200^2+100^2+50^2+25^2) = 27,200,000 floats = 6,800,000 float4
__device__ float4 g_nhwc4[6800000];

// float-element offsets of each level inside g_nhwc
#define OFF0 0
#define OFF1 20480000
#define OFF2 25600000
#define OFF3 26880000

__global__ void transpose_nchw_nhwc(const float* __restrict__ in, int H, int W,
                                    int out_off)
{
    // grid: (ceil(W/32), H, B * C/32), block (32,32)
    __shared__ float tile[32][33];
    float* out = reinterpret_cast<float*>(g_nhwc4) + out_off;

    int x  = blockIdx.x * 32 + threadIdx.x;
    int y  = blockIdx.y;
    int b  = blockIdx.z >> 3;          // C/32 = 8 tiles per batch
    int c0 = (blockIdx.z & 7) * 32;

    if (x < W) {
        size_t idx = ((size_t)(b * NCH + c0 + threadIdx.y) * H + y) * W + x;
        tile[threadIdx.y][threadIdx.x] = in[idx];
    }
    __syncthreads();

    int xo = blockIdx.x * 32 + threadIdx.y;
    if (xo < W) {
        size_t idx = (((size_t)b * H + y) * W + xo) * NCH + c0 + threadIdx.x;
        out[idx] = tile[threadIdx.x][threadIdx.y];
    }
}

__global__ void roi_align_kernel(const float* __restrict__ boxes,
                                 float* __restrict__ out)
{
    int n = blockIdx.x;                       // roi index 0..511
    float4 bx = __ldg(reinterpret_cast<const float4*>(boxes) + n);
    int b = n >> 8;                           // batch index

    // LevelMapper: floor(4 + log2(sqrt(w*h)/224) + 1e-6), clip [2,5], -2
    float s = sqrtf((bx.z - bx.x) * (bx.w - bx.y));
    int lvl = (int)floorf(4.0f + log2f(s * (1.0f / 224.0f)) + 1e-6f);
    lvl = min(max(lvl, 2), 5) - 2;

    int H;  float sc;  int off4;              // off4 in float4 units
    switch (lvl) {
        case 0:  H = 200; sc = 0.25f;    off4 = OFF0 / 4; break;
        case 1:  H = 100; sc = 0.125f;   off4 = OFF1 / 4; break;
        case 2:  H = 50;  sc = 0.0625f;  off4 = OFF2 / 4; break;
        default: H = 25;  sc = 0.03125f; off4 = OFF3 / 4; break;
    }
    const float4* f4 = g_nhwc4 + off4 + (size_t)b * H * H * (NCH / 4);

    float x1s = bx.x * sc, y1s = bx.y * sc;
    float x2s = bx.z * sc, y2s = bx.w * sc;
    float binw = fmaxf(x2s - x1s, 1.0f) * (1.0f / 7.0f);
    float binh = fmaxf(y2s - y1s, 1.0f) * (1.0f / 7.0f);
    float fH = (float)H;

    float* outn = out + (size_t)n * (NCH * 49);

    // items: 49 bins * 64 channel-groups = 3136, split across gridDim.y blocks
    for (int item = blockIdx.y * blockDim.x + threadIdx.x; item < 49 * 64;
         item += blockDim.x * gridDim.y) {
        int bin = item >> 6;
        int cg  = item & 63;                  // float4 channel group
        int oy  = bin / 7;
        int ox  = bin - oy * 7;

        float4 acc = make_float4(0.f, 0.f, 0.f, 0.f);

        #pragma unroll
        for (int iy = 0; iy < 2; iy++) {
            float yy = y1s + ((float)oy + 0.25f + 0.5f * (float)iy) * binh;
            if (yy <= -1.0f || yy >= fH) continue;   // invalid sample -> 0
            float yc = fmaxf(yy, 0.0f);
            int yl = min((int)yc, H - 1);
            int yh = min(yl + 1, H - 1);
            float ly = (yl >= H - 1) ? 0.0f : (yc - (float)yl);
            float hy = 1.0f - ly;

            #pragma unroll
            for (int ix = 0; ix < 2; ix++) {
                float xx = x1s + ((float)ox + 0.25f + 0.5f * (float)ix) * binw;
                if (xx <= -1.0f || xx >= fH) continue;
                float xc = fmaxf(xx, 0.0f);
                int xl = min((int)xc, H - 1);
                int xh = min(xl + 1, H - 1);
                float lx = (xl >= H - 1) ? 0.0f : (xc - (float)xl);
                float hx = 1.0f - lx;

                float w00 = hy * hx, w01 = hy * lx;
                float w10 = ly * hx, w11 = ly * lx;

                const float4 v00 = __ldg(&f4[((size_t)yl * H + xl) * 64 + cg]);
                const float4 v01 = __ldg(&f4[((size_t)yl * H + xh) * 64 + cg]);
                const float4 v10 = __ldg(&f4[((size_t)yh * H + xl) * 64 + cg]);
                const float4 v11 = __ldg(&f4[((size_t)yh * H + xh) * 64 + cg]);

                acc.x += w00 * v00.x + w01 * v01.x + w10 * v10.x + w11 * v11.x;
                acc.y += w00 * v00.y + w01 * v01.y + w10 * v10.y + w11 * v11.y;
                acc.z += w00 * v00.z + w01 * v01.z + w10 * v10.z + w11 * v11.z;
                acc.w += w00 * v00.w + w01 * v01.w + w10 * v10.w + w11 * v11.w;
            }
        }

        int c = cg * 4;
        outn[(c + 0) * 49 + bin] = acc.x * 0.25f;
        outn[(c + 1) * 49 + bin] = acc.y * 0.25f;
        outn[(c + 2) * 49 + bin] = acc.z * 0.25f;
        outn[(c + 3) * 49 + bin] = acc.w * 0.25f;
    }
}

extern "C" void kernel_launch(void* const* d_in, const int* in_sizes, int n_in,
                              void* d_out, int out_size)
{
    const float* f0 = (const float*)d_in[0];
    const float* f1 = (const float*)d_in[1];
    const float* f2 = (const float*)d_in[2];
    const float* f3 = (const float*)d_in[3];
    const float* boxes = (const float*)d_in[4];
    float* out = (float*)d_out;

    dim3 tb(32, 32);
    transpose_nchw_nhwc<<<dim3(7, 200, 16), tb>>>(f0, 200, 200, OFF0);
    transpose_nchw_nhwc<<<dim3(4, 100, 16), tb>>>(f1, 100, 100, OFF1);
    transpose_nchw_nhwc<<<dim3(2,  50, 16), tb>>>(f2,  50,  50, OFF2);
    transpose_nchw_nhwc<<<dim3(1,  25, 16), tb>>>(f3,  25,  25, OFF3);

    roi_align_kernel<<<dim3(512, 4), 256>>>(boxes, out);
}